// round 1
// baseline (speedup 1.0000x reference)
#include <cuda_runtime.h>
#include <math.h>

#define BB 2
#define LL 2048
#define DD 1024
#define HH 16
#define DHH 64
#define ROWS (BB*LL)   // 4096

// Scratch (allocation-free rule: __device__ globals)
__device__ float g_q[ROWS*DD];
__device__ float g_k[ROWS*DD];
__device__ float g_v[ROWS*DD];
__device__ float g_attn[ROWS*DD];

// ---------------------------------------------------------------------------
// SGEMM: C[M,N] = scale * A[M,K] @ W[K,N]; BM=BN=64, BK=16, 256 thr, 4x4 micro
// ---------------------------------------------------------------------------
__global__ __launch_bounds__(256) void sgemm64(
    const float* __restrict__ A, const float* __restrict__ W,
    float* __restrict__ C, int M, int N, int K, float scale)
{
    const int LD = 68;  // padded row (68*4B = 272B, 16B-aligned rows)
    __shared__ __align__(16) float As[16 * 68];  // transposed: As[k][m]
    __shared__ __align__(16) float Bs[16 * 68];  // Bs[k][n]

    int tid = threadIdx.x;
    int tx = tid & 15, ty = tid >> 4;
    int bm = blockIdx.y * 64, bn = blockIdx.x * 64;

    float acc[4][4] = {{0.f}};

    int a_row = tid >> 2, a_k4 = tid & 3;     // 64 rows x 4 float4 of k
    int b_row = tid >> 4, b_c4 = tid & 15;    // 16 k-rows x 16 float4 of n

    const float* Aptr = A + (long long)(bm + a_row) * K + a_k4 * 4;
    const float* Bptr = W + (long long)b_row * N + bn + b_c4 * 4;

    for (int k0 = 0; k0 < K; k0 += 16) {
        float4 av = *reinterpret_cast<const float4*>(Aptr + k0);
        As[(a_k4 * 4 + 0) * LD + a_row] = av.x;
        As[(a_k4 * 4 + 1) * LD + a_row] = av.y;
        As[(a_k4 * 4 + 2) * LD + a_row] = av.z;
        As[(a_k4 * 4 + 3) * LD + a_row] = av.w;
        *reinterpret_cast<float4*>(&Bs[b_row * LD + b_c4 * 4]) =
            *reinterpret_cast<const float4*>(Bptr + (long long)k0 * N);
        __syncthreads();

        #pragma unroll
        for (int kk = 0; kk < 16; kk++) {
            float4 a = *reinterpret_cast<float4*>(&As[kk * LD + ty * 4]);
            float4 b = *reinterpret_cast<float4*>(&Bs[kk * LD + tx * 4]);
            acc[0][0] += a.x * b.x; acc[0][1] += a.x * b.y; acc[0][2] += a.x * b.z; acc[0][3] += a.x * b.w;
            acc[1][0] += a.y * b.x; acc[1][1] += a.y * b.y; acc[1][2] += a.y * b.z; acc[1][3] += a.y * b.w;
            acc[2][0] += a.z * b.x; acc[2][1] += a.z * b.y; acc[2][2] += a.z * b.z; acc[2][3] += a.z * b.w;
            acc[3][0] += a.w * b.x; acc[3][1] += a.w * b.y; acc[3][2] += a.w * b.z; acc[3][3] += a.w * b.w;
        }
        __syncthreads();
    }

    #pragma unroll
    for (int i = 0; i < 4; i++) {
        float4 r = make_float4(acc[i][0] * scale, acc[i][1] * scale,
                               acc[i][2] * scale, acc[i][3] * scale);
        *reinterpret_cast<float4*>(
            &C[(long long)(bm + ty * 4 + i) * N + bn + tx * 4]) = r;
    }
}

// ---------------------------------------------------------------------------
// Flash attention: one block = 64 query rows of one (b,h); loops 64-key tiles
// with online softmax. Q/K in smem transposed [dh][row]; V row-major; P
// transposed [key][row] for the PV GEMM. 256 threads, 4x4 micro-tiles.
// ---------------------------------------------------------------------------
__global__ __launch_bounds__(256) void attn64(
    const float* __restrict__ Q, const float* __restrict__ Kg,
    const float* __restrict__ Vg, const float* __restrict__ bias,
    float* __restrict__ O)
{
    const int LD = 68;
    extern __shared__ __align__(16) float smem[];
    float* Qs = smem;               // [64 dh][68]
    float* Ks = Qs + 64 * LD;       // [64 dh][68]
    float* Vs = Ks + 64 * LD;       // [64 key][68]
    float* Pt = Vs + 64 * LD;       // [64 key][68]

    int tid = threadIdx.x;
    int tx = tid & 15, ty = tid >> 4;
    int bh = blockIdx.y;
    int b = bh >> 4, h = bh & 15;
    int q0 = blockIdx.x * 64;

    const float* qbase = Q  + ((long long)(b * LL + q0)) * DD + h * DHH;
    const float* kbase = Kg + ((long long)b * LL) * DD + h * DHH;
    const float* vbase = Vg + ((long long)b * LL) * DD + h * DHH;

    // Load Q tile transposed (once per block)
    {
        int r = tid >> 4, d4 = tid & 15;
        #pragma unroll
        for (int it = 0; it < 4; it++) {
            int qr = it * 16 + r;
            float4 qv = *reinterpret_cast<const float4*>(qbase + (long long)qr * DD + d4 * 4);
            Qs[(d4 * 4 + 0) * LD + qr] = qv.x;
            Qs[(d4 * 4 + 1) * LD + qr] = qv.y;
            Qs[(d4 * 4 + 2) * LD + qr] = qv.z;
            Qs[(d4 * 4 + 3) * LD + qr] = qv.w;
        }
    }

    float m[4], l[4], o[4][4];
    #pragma unroll
    for (int i = 0; i < 4; i++) {
        m[i] = -INFINITY; l[i] = 0.f;
        #pragma unroll
        for (int j = 0; j < 4; j++) o[i][j] = 0.f;
    }
    __syncthreads();

    for (int k0 = 0; k0 < LL; k0 += 64) {
        // Load K (transposed) and V (row-major) tiles
        {
            int r = tid >> 4, d4 = tid & 15;
            #pragma unroll
            for (int it = 0; it < 4; it++) {
                int kr = it * 16 + r;
                const float* kp = kbase + (long long)(k0 + kr) * DD + d4 * 4;
                float4 kv = *reinterpret_cast<const float4*>(kp);
                Ks[(d4 * 4 + 0) * LD + kr] = kv.x;
                Ks[(d4 * 4 + 1) * LD + kr] = kv.y;
                Ks[(d4 * 4 + 2) * LD + kr] = kv.z;
                Ks[(d4 * 4 + 3) * LD + kr] = kv.w;
                const float* vp = vbase + (long long)(k0 + kr) * DD + d4 * 4;
                *reinterpret_cast<float4*>(&Vs[kr * LD + d4 * 4]) =
                    *reinterpret_cast<const float4*>(vp);
            }
        }
        __syncthreads();

        // S = Q @ K^T (4x4 micro over 64-deep dh)
        float s[4][4] = {{0.f}};
        #pragma unroll 8
        for (int d = 0; d < 64; d++) {
            float4 a = *reinterpret_cast<float4*>(&Qs[d * LD + ty * 4]);
            float4 bb = *reinterpret_cast<float4*>(&Ks[d * LD + tx * 4]);
            s[0][0] += a.x * bb.x; s[0][1] += a.x * bb.y; s[0][2] += a.x * bb.z; s[0][3] += a.x * bb.w;
            s[1][0] += a.y * bb.x; s[1][1] += a.y * bb.y; s[1][2] += a.y * bb.z; s[1][3] += a.y * bb.w;
            s[2][0] += a.z * bb.x; s[2][1] += a.z * bb.y; s[2][2] += a.z * bb.z; s[2][3] += a.z * bb.w;
            s[3][0] += a.w * bb.x; s[3][1] += a.w * bb.y; s[3][2] += a.w * bb.z; s[3][3] += a.w * bb.w;
        }

        // + bias (broadcast over b,h -> stays L2-resident)
        #pragma unroll
        for (int i = 0; i < 4; i++) {
            float4 bv = *reinterpret_cast<const float4*>(
                &bias[(long long)(q0 + ty * 4 + i) * LL + k0 + tx * 4]);
            s[i][0] += bv.x; s[i][1] += bv.y; s[i][2] += bv.z; s[i][3] += bv.w;
        }

        // Online softmax update. Row spans 16 lanes (tx), same half-warp:
        // lane = (ty&1)*16 + tx, so xor {1,2,4,8} stays within the row group.
        #pragma unroll
        for (int i = 0; i < 4; i++) {
            float tm = fmaxf(fmaxf(s[i][0], s[i][1]), fmaxf(s[i][2], s[i][3]));
            tm = fmaxf(tm, __shfl_xor_sync(0xffffffffu, tm, 1));
            tm = fmaxf(tm, __shfl_xor_sync(0xffffffffu, tm, 2));
            tm = fmaxf(tm, __shfl_xor_sync(0xffffffffu, tm, 4));
            tm = fmaxf(tm, __shfl_xor_sync(0xffffffffu, tm, 8));
            float mn = fmaxf(m[i], tm);
            float alpha = __expf(m[i] - mn);
            float ps = 0.f;
            #pragma unroll
            for (int j = 0; j < 4; j++) { s[i][j] = __expf(s[i][j] - mn); ps += s[i][j]; }
            ps += __shfl_xor_sync(0xffffffffu, ps, 1);
            ps += __shfl_xor_sync(0xffffffffu, ps, 2);
            ps += __shfl_xor_sync(0xffffffffu, ps, 4);
            ps += __shfl_xor_sync(0xffffffffu, ps, 8);
            l[i] = l[i] * alpha + ps;
            m[i] = mn;
            #pragma unroll
            for (int j = 0; j < 4; j++) o[i][j] *= alpha;
        }

        // Store P transposed [key][row]
        #pragma unroll
        for (int i = 0; i < 4; i++)
            #pragma unroll
            for (int j = 0; j < 4; j++)
                Pt[(tx * 4 + j) * LD + ty * 4 + i] = s[i][j];
        __syncthreads();

        // O += P @ V
        #pragma unroll 8
        for (int c = 0; c < 64; c++) {
            float4 p  = *reinterpret_cast<float4*>(&Pt[c * LD + ty * 4]);
            float4 vv = *reinterpret_cast<float4*>(&Vs[c * LD + tx * 4]);
            o[0][0] += p.x * vv.x; o[0][1] += p.x * vv.y; o[0][2] += p.x * vv.z; o[0][3] += p.x * vv.w;
            o[1][0] += p.y * vv.x; o[1][1] += p.y * vv.y; o[1][2] += p.y * vv.z; o[1][3] += p.y * vv.w;
            o[2][0] += p.z * vv.x; o[2][1] += p.z * vv.y; o[2][2] += p.z * vv.z; o[2][3] += p.z * vv.w;
            o[3][0] += p.w * vv.x; o[3][1] += p.w * vv.y; o[3][2] += p.w * vv.z; o[3][3] += p.w * vv.w;
        }
        __syncthreads();
    }

    // Normalize and write out in [B, L, H*DH] layout
    float* obase = O + ((long long)(b * LL + q0)) * DD + h * DHH;
    #pragma unroll
    for (int i = 0; i < 4; i++) {
        float inv = 1.0f / l[i];
        float4 r = make_float4(o[i][0] * inv, o[i][1] * inv,
                               o[i][2] * inv, o[i][3] * inv);
        *reinterpret_cast<float4*>(&obase[(long long)(ty * 4 + i) * DD + tx * 4]) = r;
    }
}

// ---------------------------------------------------------------------------
extern "C" void kernel_launch(void* const* d_in, const int* in_sizes, int n_in,
                              void* d_out, int out_size)
{
    const float* xq   = (const float*)d_in[0];  // query_antecedent [B,L,D]
    const float* xm   = (const float*)d_in[1];  // memory_antecedent [B,L,D]
    const float* bias = (const float*)d_in[2];  // [1,1,L,L]
    const float* Wq   = (const float*)d_in[3];
    const float* Wk   = (const float*)d_in[4];
    const float* Wv   = (const float*)d_in[5];
    const float* Wo   = (const float*)d_in[6];
    float* out = (float*)d_out;

    float *q, *k, *v, *attn;
    cudaGetSymbolAddress((void**)&q,    g_q);
    cudaGetSymbolAddress((void**)&k,    g_k);
    cudaGetSymbolAddress((void**)&v,    g_v);
    cudaGetSymbolAddress((void**)&attn, g_attn);

    dim3 gg(DD / 64, ROWS / 64);  // (16, 64)
    // Q projection includes d_head^-0.5 = 0.125 scaling
    sgemm64<<<gg, 256>>>(xq, Wq, q, ROWS, DD, DD, 0.125f);
    sgemm64<<<gg, 256>>>(xm, Wk, k, ROWS, DD, DD, 1.0f);
    sgemm64<<<gg, 256>>>(xm, Wv, v, ROWS, DD, DD, 1.0f);

    const size_t SMEM = 4ull * 64 * 68 * sizeof(float);  // 69632 B
    cudaFuncSetAttribute(attn64, cudaFuncAttributeMaxDynamicSharedMemorySize, (int)SMEM);
    dim3 ga(LL / 64, BB * HH);    // (32, 32)
    attn64<<<ga, 256, SMEM>>>(q, k, v, bias, attn);

    sgemm64<<<gg, 256>>>(attn, Wo, out, ROWS, DD, DD, 1.0f);
}

// round 3
// speedup vs baseline: 2.5352x; 2.5352x over previous
#include <cuda_runtime.h>
#include <math.h>
#include <stdint.h>

#define BB 2
#define LL 2048
#define DD 1024
#define HH 16
#define DHH 64
#define ROWS (BB*LL)   // 4096

// Scratch (allocation-free rule: __device__ globals)
__device__ float g_q[ROWS*DD];
__device__ float g_k[ROWS*DD];
__device__ float g_v[ROWS*DD];
__device__ float g_attn[ROWS*DD];
__device__ float g_xq[ROWS*DD];
__device__ float g_xm[ROWS*DD];
__device__ float g_wq[DD*DD];
__device__ float g_wk[DD*DD];
__device__ float g_wv[DD*DD];
__device__ float g_wo[DD*DD];

// ===========================================================================
// Helpers (plain compute_103 PTX only: mma.sync, cp.async, cvt — no tcgen05)
// ===========================================================================
__device__ __forceinline__ uint32_t smem_u32(const void* p) {
    uint32_t a;
    asm("{ .reg .u64 t; cvta.to.shared.u64 t, %1; cvt.u32.u64 %0, t; }"
        : "=r"(a) : "l"(p));
    return a;
}
__device__ __forceinline__ float to_tf32(float x) {
    uint32_t u;
    asm("cvt.rna.tf32.f32 %0, %1;" : "=r"(u) : "f"(x));
    return __uint_as_float(u);
}
__device__ __forceinline__ void mma_tf32(float c[4],
    uint32_t a0, uint32_t a1, uint32_t a2, uint32_t a3,
    uint32_t b0, uint32_t b1)
{
    asm volatile(
        "mma.sync.aligned.m16n8k8.row.col.f32.tf32.tf32.f32 "
        "{%0,%1,%2,%3}, {%4,%5,%6,%7}, {%8,%9}, {%0,%1,%2,%3};"
        : "+f"(c[0]), "+f"(c[1]), "+f"(c[2]), "+f"(c[3])
        : "r"(a0), "r"(a1), "r"(a2), "r"(a3), "r"(b0), "r"(b1));
}
__device__ __forceinline__ void cp_async16(uint32_t s, const void* g) {
    asm volatile("cp.async.cg.shared.global [%0], [%1], 16;" :: "r"(s), "l"(g));
}
#define CP_COMMIT() asm volatile("cp.async.commit_group;" ::: "memory")
#define CP_WAIT(n)  asm volatile("cp.async.wait_group %0;" :: "n"(n) : "memory")

// ===========================================================================
// Prep: round fp32 buffer to tf32 (rna) so mma inputs are pre-rounded
// ===========================================================================
__global__ __launch_bounds__(256) void round_tf32(
    const float* __restrict__ src, float* __restrict__ dst, int n4)
{
    int i = blockIdx.x * blockDim.x + threadIdx.x;
    if (i < n4) {
        float4 v = reinterpret_cast<const float4*>(src)[i];
        v.x = to_tf32(v.x); v.y = to_tf32(v.y);
        v.z = to_tf32(v.z); v.w = to_tf32(v.w);
        reinterpret_cast<float4*>(dst)[i] = v;
    }
}

// ===========================================================================
// tf32 mma.sync GEMM: C[M,N] = scale * A[M,K] @ B[K,N]
// M=4096, N=K=1024. Block 128x128x32, 8 warps (warp tile 32x64), cp.async x2.
// smem: As[m][k] LDA=36 (conflict-free reads+writes), Bs[k][n] LDB=136.
// ===========================================================================
#define GBM 128
#define GBN 128
#define GBK 32
#define LDA 36
#define LDB 136

__global__ __launch_bounds__(256, 1) void gemm_mma(
    const float* __restrict__ A, const float* __restrict__ B,
    float* __restrict__ C, float scale, int round_out)
{
    extern __shared__ float sm[];
    float* As = sm;                       // [2][128*36]
    float* Bs = sm + 2 * GBM * LDA;       // [2][32*136]

    const int tid = threadIdx.x, lane = tid & 31, wid = tid >> 5;
    const int wm = wid & 3, wn = wid >> 2;   // warp: 32-row strip, 64-col strip
    const int tg = lane >> 2, tk = lane & 3; // groupID, threadInGroup

    const long long bm = (long long)blockIdx.y * GBM;
    const long long bn = (long long)blockIdx.x * GBN;

    float c[2][8][4];
    #pragma unroll
    for (int i = 0; i < 2; i++)
        #pragma unroll
        for (int j = 0; j < 8; j++)
            #pragma unroll
            for (int r = 0; r < 4; r++) c[i][j][r] = 0.f;

    // stage K-tile k0 into buffer buf
    auto stage = [&](int buf, int k0) {
        float* a = As + buf * GBM * LDA;
        float* b = Bs + buf * GBK * LDB;
        #pragma unroll
        for (int it = 0; it < 4; it++) {          // A: 128x32 = 1024 f4
            int f = it * 256 + tid, row = f >> 3, c4 = f & 7;
            cp_async16(smem_u32(a + row * LDA + c4 * 4),
                       A + (bm + row) * DD + k0 + c4 * 4);
        }
        #pragma unroll
        for (int it = 0; it < 4; it++) {          // B: 32x128 = 1024 f4
            int f = it * 256 + tid, kr = f >> 5, c4 = f & 31;
            cp_async16(smem_u32(b + kr * LDB + c4 * 4),
                       B + (long long)(k0 + kr) * DD + bn + c4 * 4);
        }
    };

    stage(0, 0);
    CP_COMMIT();

    const int NKT = DD / GBK;  // 32
    for (int kt = 0; kt < NKT; kt++) {
        int buf = kt & 1;
        if (kt + 1 < NKT) { stage(buf ^ 1, (kt + 1) * GBK); CP_COMMIT(); CP_WAIT(1); }
        else             { CP_WAIT(0); }
        __syncthreads();

        const float* a = As + buf * GBM * LDA + (wm * 32) * LDA;
        const float* b = Bs + buf * GBK * LDB + wn * 64;

        #pragma unroll
        for (int k8 = 0; k8 < 4; k8++) {
            uint32_t av[2][4];
            #pragma unroll
            for (int mi = 0; mi < 2; mi++) {
                const float* ap = a + (mi * 16 + tg) * LDA + k8 * 8 + tk;
                av[mi][0] = __float_as_uint(ap[0]);
                av[mi][1] = __float_as_uint(ap[8 * LDA]);
                av[mi][2] = __float_as_uint(ap[4]);
                av[mi][3] = __float_as_uint(ap[8 * LDA + 4]);
            }
            #pragma unroll
            for (int nj = 0; nj < 8; nj++) {
                const float* bp = b + (k8 * 8 + tk) * LDB + nj * 8 + tg;
                uint32_t b0 = __float_as_uint(bp[0]);
                uint32_t b1 = __float_as_uint(bp[4 * LDB]);
                mma_tf32(c[0][nj], av[0][0], av[0][1], av[0][2], av[0][3], b0, b1);
                mma_tf32(c[1][nj], av[1][0], av[1][1], av[1][2], av[1][3], b0, b1);
            }
        }
        __syncthreads();
    }

    // Epilogue
    #pragma unroll
    for (int mi = 0; mi < 2; mi++) {
        long long row = bm + wm * 32 + mi * 16 + tg;
        #pragma unroll
        for (int nj = 0; nj < 8; nj++) {
            long long col = bn + wn * 64 + nj * 8 + 2 * tk;
            float2 v0 = make_float2(c[mi][nj][0] * scale, c[mi][nj][1] * scale);
            float2 v1 = make_float2(c[mi][nj][2] * scale, c[mi][nj][3] * scale);
            if (round_out) {
                v0.x = to_tf32(v0.x); v0.y = to_tf32(v0.y);
                v1.x = to_tf32(v1.x); v1.y = to_tf32(v1.y);
            }
            *reinterpret_cast<float2*>(&C[row * DD + col]) = v0;
            *reinterpret_cast<float2*>(&C[(row + 8) * DD + col]) = v1;
        }
    }
}

// ===========================================================================
// Flash attention, tf32 mma.sync. CTA = 128 q-rows of one (b,h), 8 warps
// (warp = 16 q-rows). 64-key tiles, online softmax on C-fragments,
// P routed through per-warp smem (C-frag -> A-frag layout).
// ===========================================================================
#define ALDK 68   // pitch for Qs/Ks/Ps (conflict-free for their access patterns)
#define ALDV 72   // pitch for Vs

__global__ __launch_bounds__(256, 1) void attn_mma(
    const float* __restrict__ Q, const float* __restrict__ K,
    const float* __restrict__ V, const float* __restrict__ bias,
    float* __restrict__ O)
{
    extern __shared__ float sm[];
    float* Qs = sm;                        // [128][68]
    float* Ks = Qs + 128 * ALDK;           // [64][68]
    float* Vs = Ks + 64 * ALDK;            // [64][72]
    float* Ps = Vs + 64 * ALDV;            // [128][68]

    const int tid = threadIdx.x, lane = tid & 31, wid = tid >> 5;
    const int tg = lane >> 2, tk = lane & 3;
    const int bh = blockIdx.y, b = bh >> 4, h = bh & 15;
    const int q0 = blockIdx.x * 128;

    const float* qbase = Q + ((long long)(b * LL + q0)) * DD + h * DHH;
    const float* kbase = K + ((long long)(b * LL)) * DD + h * DHH;
    const float* vbase = V + ((long long)(b * LL)) * DD + h * DHH;

    // Stage Q (tf32-rounded already): 128 rows x 16 f4
    #pragma unroll
    for (int it = 0; it < 8; it++) {
        int f = it * 256 + tid, row = f >> 4, c4 = f & 15;
        *reinterpret_cast<float4*>(&Qs[row * ALDK + c4 * 4]) =
            *reinterpret_cast<const float4*>(qbase + (long long)row * DD + c4 * 4);
    }

    float m0 = -INFINITY, m1 = -INFINITY, l0 = 0.f, l1 = 0.f;
    float o[8][4];
    #pragma unroll
    for (int j = 0; j < 8; j++)
        #pragma unroll
        for (int r = 0; r < 4; r++) o[j][r] = 0.f;

    float* Qw = Qs + wid * 16 * ALDK;
    float* Pw = Ps + wid * 16 * ALDK;

    for (int kt = 0; kt < LL / 64; kt++) {
        const int k0 = kt * 64;
        __syncthreads();   // prior tile's K/V reads complete
        #pragma unroll
        for (int it = 0; it < 4; it++) {   // K,V: 64 rows x 16 f4 each
            int f = it * 256 + tid, row = f >> 4, c4 = f & 15;
            *reinterpret_cast<float4*>(&Ks[row * ALDK + c4 * 4]) =
                *reinterpret_cast<const float4*>(kbase + (long long)(k0 + row) * DD + c4 * 4);
            *reinterpret_cast<float4*>(&Vs[row * ALDV + c4 * 4]) =
                *reinterpret_cast<const float4*>(vbase + (long long)(k0 + row) * DD + c4 * 4);
        }
        __syncthreads();

        // S = Q @ K^T : warp computes 16x64
        float s[8][4];
        #pragma unroll
        for (int j = 0; j < 8; j++)
            #pragma unroll
            for (int r = 0; r < 4; r++) s[j][r] = 0.f;

        #pragma unroll
        for (int k8 = 0; k8 < 8; k8++) {
            const float* ap = Qw + tg * ALDK + k8 * 8 + tk;
            uint32_t a0 = __float_as_uint(ap[0]);
            uint32_t a1 = __float_as_uint(ap[8 * ALDK]);
            uint32_t a2 = __float_as_uint(ap[4]);
            uint32_t a3 = __float_as_uint(ap[8 * ALDK + 4]);
            #pragma unroll
            for (int nj = 0; nj < 8; nj++) {
                const float* bp = Ks + (nj * 8 + tg) * ALDK + k8 * 8 + tk;
                uint32_t b0 = __float_as_uint(bp[0]);
                uint32_t b1 = __float_as_uint(bp[4]);
                mma_tf32(s[nj], a0, a1, a2, a3, b0, b1);
            }
        }

        // + bias
        {
            const float* bp = bias + (long long)(q0 + wid * 16 + tg) * LL
                              + k0 + 2 * tk;
            #pragma unroll
            for (int nj = 0; nj < 8; nj++) {
                float2 bv0 = *reinterpret_cast<const float2*>(bp + nj * 8);
                float2 bv1 = *reinterpret_cast<const float2*>(bp + 8 * (long long)LL + nj * 8);
                s[nj][0] += bv0.x; s[nj][1] += bv0.y;
                s[nj][2] += bv1.x; s[nj][3] += bv1.y;
            }
        }

        // Online softmax (rows tg and tg+8; quad = lanes {4tg..4tg+3})
        float r0 = -INFINITY, r1 = -INFINITY;
        #pragma unroll
        for (int nj = 0; nj < 8; nj++) {
            r0 = fmaxf(r0, fmaxf(s[nj][0], s[nj][1]));
            r1 = fmaxf(r1, fmaxf(s[nj][2], s[nj][3]));
        }
        r0 = fmaxf(r0, __shfl_xor_sync(0xffffffffu, r0, 1));
        r0 = fmaxf(r0, __shfl_xor_sync(0xffffffffu, r0, 2));
        r1 = fmaxf(r1, __shfl_xor_sync(0xffffffffu, r1, 1));
        r1 = fmaxf(r1, __shfl_xor_sync(0xffffffffu, r1, 2));
        float m0n = fmaxf(m0, r0), m1n = fmaxf(m1, r1);
        float al0 = __expf(m0 - m0n), al1 = __expf(m1 - m1n);
        float s0 = 0.f, s1 = 0.f;
        #pragma unroll
        for (int nj = 0; nj < 8; nj++) {
            s[nj][0] = __expf(s[nj][0] - m0n);
            s[nj][1] = __expf(s[nj][1] - m0n);
            s[nj][2] = __expf(s[nj][2] - m1n);
            s[nj][3] = __expf(s[nj][3] - m1n);
            s0 += s[nj][0] + s[nj][1];
            s1 += s[nj][2] + s[nj][3];
        }
        s0 += __shfl_xor_sync(0xffffffffu, s0, 1);
        s0 += __shfl_xor_sync(0xffffffffu, s0, 2);
        s1 += __shfl_xor_sync(0xffffffffu, s1, 1);
        s1 += __shfl_xor_sync(0xffffffffu, s1, 2);
        l0 = l0 * al0 + s0;  l1 = l1 * al1 + s1;
        m0 = m0n;  m1 = m1n;
        #pragma unroll
        for (int nj = 0; nj < 8; nj++) {
            o[nj][0] *= al0; o[nj][1] *= al0;
            o[nj][2] *= al1; o[nj][3] *= al1;
        }

        // P -> per-warp smem (C-frag layout -> A-frag layout), tf32-rounded
        __syncwarp();
        #pragma unroll
        for (int nj = 0; nj < 8; nj++) {
            *reinterpret_cast<float2*>(&Pw[tg * ALDK + nj * 8 + 2 * tk]) =
                make_float2(to_tf32(s[nj][0]), to_tf32(s[nj][1]));
            *reinterpret_cast<float2*>(&Pw[(tg + 8) * ALDK + nj * 8 + 2 * tk]) =
                make_float2(to_tf32(s[nj][2]), to_tf32(s[nj][3]));
        }
        __syncwarp();

        // O += P @ V
        #pragma unroll
        for (int k8 = 0; k8 < 8; k8++) {
            const float* ap = Pw + tg * ALDK + k8 * 8 + tk;
            uint32_t a0 = __float_as_uint(ap[0]);
            uint32_t a1 = __float_as_uint(ap[8 * ALDK]);
            uint32_t a2 = __float_as_uint(ap[4]);
            uint32_t a3 = __float_as_uint(ap[8 * ALDK + 4]);
            #pragma unroll
            for (int nj = 0; nj < 8; nj++) {
                const float* bp = Vs + (k8 * 8 + tk) * ALDV + nj * 8 + tg;
                uint32_t b0 = __float_as_uint(bp[0]);
                uint32_t b1 = __float_as_uint(bp[4 * ALDV]);
                mma_tf32(o[nj], a0, a1, a2, a3, b0, b1);
            }
        }
    }

    // Epilogue: normalize, round to tf32 (feeds final GEMM), store
    float inv0 = 1.f / l0, inv1 = 1.f / l1;
    float* ob = O + ((long long)(b * LL + q0 + wid * 16 + tg)) * DD + h * DHH;
    #pragma unroll
    for (int nj = 0; nj < 8; nj++) {
        float2 v0 = make_float2(to_tf32(o[nj][0] * inv0), to_tf32(o[nj][1] * inv0));
        float2 v1 = make_float2(to_tf32(o[nj][2] * inv1), to_tf32(o[nj][3] * inv1));
        *reinterpret_cast<float2*>(&ob[nj * 8 + 2 * tk]) = v0;
        *reinterpret_cast<float2*>(&ob[8 * DD + nj * 8 + 2 * tk]) = v1;
    }
}

// ---------------------------------------------------------------------------
extern "C" void kernel_launch(void* const* d_in, const int* in_sizes, int n_in,
                              void* d_out, int out_size)
{
    const float* xq   = (const float*)d_in[0];
    const float* xm   = (const float*)d_in[1];
    const float* bias = (const float*)d_in[2];
    const float* Wq   = (const float*)d_in[3];
    const float* Wk   = (const float*)d_in[4];
    const float* Wv   = (const float*)d_in[5];
    const float* Wo   = (const float*)d_in[6];
    float* out = (float*)d_out;

    float *q, *k, *v, *attn, *rxq, *rxm, *rwq, *rwk, *rwv, *rwo;
    cudaGetSymbolAddress((void**)&q,    g_q);
    cudaGetSymbolAddress((void**)&k,    g_k);
    cudaGetSymbolAddress((void**)&v,    g_v);
    cudaGetSymbolAddress((void**)&attn, g_attn);
    cudaGetSymbolAddress((void**)&rxq,  g_xq);
    cudaGetSymbolAddress((void**)&rxm,  g_xm);
    cudaGetSymbolAddress((void**)&rwq,  g_wq);
    cudaGetSymbolAddress((void**)&rwk,  g_wk);
    cudaGetSymbolAddress((void**)&rwv,  g_wv);
    cudaGetSymbolAddress((void**)&rwo,  g_wo);

    // 1) Pre-round all mma inputs to tf32 (rna)
    const int N4X = ROWS * DD / 4, N4W = DD * DD / 4;
    round_tf32<<<(N4X + 255) / 256, 256>>>(xq, rxq, N4X);
    round_tf32<<<(N4X + 255) / 256, 256>>>(xm, rxm, N4X);
    round_tf32<<<(N4W + 255) / 256, 256>>>(Wq, rwq, N4W);
    round_tf32<<<(N4W + 255) / 256, 256>>>(Wk, rwk, N4W);
    round_tf32<<<(N4W + 255) / 256, 256>>>(Wv, rwv, N4W);
    round_tf32<<<(N4W + 255) / 256, 256>>>(Wo, rwo, N4W);

    // 2) Projections (epilogue rounds outputs to tf32 for attention mma)
    const int GEMM_SMEM = (2 * GBM * LDA + 2 * GBK * LDB) * 4;  // 71680
    cudaFuncSetAttribute(gemm_mma, cudaFuncAttributeMaxDynamicSharedMemorySize, GEMM_SMEM);
    dim3 gg(DD / GBN, ROWS / GBM);   // (8, 32)
    gemm_mma<<<gg, 256, GEMM_SMEM>>>(rxq, rwq, q, 0.125f, 1);
    gemm_mma<<<gg, 256, GEMM_SMEM>>>(rxm, rwk, k, 1.0f, 1);
    gemm_mma<<<gg, 256, GEMM_SMEM>>>(rxm, rwv, v, 1.0f, 1);

    // 3) Attention (tf32 mma flash)
    const int ATTN_SMEM = (128 * ALDK + 64 * ALDK + 64 * ALDV + 128 * ALDK) * 4; // 105472
    cudaFuncSetAttribute(attn_mma, cudaFuncAttributeMaxDynamicSharedMemorySize, ATTN_SMEM);
    dim3 ga(LL / 128, BB * HH);      // (16, 32)
    attn_mma<<<ga, 256, ATTN_SMEM>>>(q, k, v, bias, attn);

    // 4) Output projection (no rounding — final answer)
    gemm_mma<<<gg, 256, GEMM_SMEM>>>(attn, rwo, out, 1.0f, 0);
}

// round 4
// speedup vs baseline: 2.7509x; 1.0851x over previous
#include <cuda_runtime.h>
#include <math.h>
#include <stdint.h>

#define BB 2
#define LL 2048
#define DD 1024
#define HH 16
#define DHH 64
#define ROWS (BB*LL)   // 4096

// Scratch (allocation-free rule: __device__ globals)
__device__ float g_q[ROWS*DD];
__device__ float g_k[ROWS*DD];
__device__ float g_v[ROWS*DD];
__device__ float g_attn[ROWS*DD];
__device__ float g_xq[ROWS*DD];
__device__ float g_xm[ROWS*DD];
__device__ float g_wq[DD*DD];   // transposed [n][k], tf32-rounded
__device__ float g_wk[DD*DD];
__device__ float g_wv[DD*DD];
__device__ float g_wo[DD*DD];

// ===========================================================================
// Helpers (plain compute_103 PTX: mma.sync, ldmatrix, cp.async — no tcgen05)
// ===========================================================================
__device__ __forceinline__ uint32_t smem_u32(const void* p) {
    uint32_t a;
    asm("{ .reg .u64 t; cvta.to.shared.u64 t, %1; cvt.u32.u64 %0, t; }"
        : "=r"(a) : "l"(p));
    return a;
}
__device__ __forceinline__ float to_tf32(float x) {
    uint32_t u;
    asm("cvt.rna.tf32.f32 %0, %1;" : "=r"(u) : "f"(x));
    return __uint_as_float(u);
}
__device__ __forceinline__ void mma_tf32(float c[4],
    uint32_t a0, uint32_t a1, uint32_t a2, uint32_t a3,
    uint32_t b0, uint32_t b1)
{
    asm volatile(
        "mma.sync.aligned.m16n8k8.row.col.f32.tf32.tf32.f32 "
        "{%0,%1,%2,%3}, {%4,%5,%6,%7}, {%8,%9}, {%0,%1,%2,%3};"
        : "+f"(c[0]), "+f"(c[1]), "+f"(c[2]), "+f"(c[3])
        : "r"(a0), "r"(a1), "r"(a2), "r"(a3), "r"(b0), "r"(b1));
}
#define LDSM_X4(r, addr) \
    asm volatile("ldmatrix.sync.aligned.m8n8.x4.shared.b16 {%0,%1,%2,%3}, [%4];" \
        : "=r"((r)[0]), "=r"((r)[1]), "=r"((r)[2]), "=r"((r)[3]) : "r"(addr))
__device__ __forceinline__ void cp_async16(uint32_t s, const void* g) {
    asm volatile("cp.async.cg.shared.global [%0], [%1], 16;" :: "r"(s), "l"(g));
}
#define CP_COMMIT() asm volatile("cp.async.commit_group;" ::: "memory")
#define CP_WAIT0()  asm volatile("cp.async.wait_group 0;" ::: "memory")
#define CP_WAIT1()  asm volatile("cp.async.wait_group 1;" ::: "memory")

// ===========================================================================
// Prep kernels
// ===========================================================================
__global__ __launch_bounds__(256) void round_tf32(
    const float* __restrict__ src, float* __restrict__ dst, int n4)
{
    int i = blockIdx.x * blockDim.x + threadIdx.x;
    if (i < n4) {
        float4 v = reinterpret_cast<const float4*>(src)[i];
        v.x = to_tf32(v.x); v.y = to_tf32(v.y);
        v.z = to_tf32(v.z); v.w = to_tf32(v.w);
        reinterpret_cast<float4*>(dst)[i] = v;
    }
}

// Wt[n][k] = tf32(W[k][n]), 1024x1024
__global__ __launch_bounds__(256) void transpose_tf32(
    const float* __restrict__ W, float* __restrict__ Wt)
{
    __shared__ float t[32][33];
    int x = blockIdx.x * 32 + threadIdx.x;
    int y = blockIdx.y * 32 + threadIdx.y;
    #pragma unroll
    for (int i = 0; i < 32; i += 8)
        t[threadIdx.y + i][threadIdx.x] = W[(long long)(y + i) * DD + x];
    __syncthreads();
    x = blockIdx.y * 32 + threadIdx.x;
    y = blockIdx.x * 32 + threadIdx.y;
    #pragma unroll
    for (int i = 0; i < 32; i += 8)
        Wt[(long long)(y + i) * DD + x] = to_tf32(t[threadIdx.x][threadIdx.y + i]);
}

// ===========================================================================
// tf32 mma GEMM: C[M,N] = scale * A[M,K] @ Bt[N,K]^T
// Block 128x128x32, 128 thr (4 warps, warp tile 64x64), 3-stage cp.async,
// ldmatrix.x4 fragment loads. LDA=36 floats => conflict-free everywhere.
// ===========================================================================
#define GBK 32
#define LDA 36
#define TILEF (128 * LDA)           // floats per (A or B) stage tile

__global__ __launch_bounds__(128, 2) void gemm_mma(
    const float* __restrict__ A, const float* __restrict__ Bt,
    float* __restrict__ C, float scale, int round_out)
{
    extern __shared__ float sm[];   // 3 stages x (A tile + B tile)

    const int tid = threadIdx.x, lane = tid & 31, wid = tid >> 5;
    const int wr = (wid & 1) * 64, wc = (wid >> 1) * 64;
    const int tg = lane >> 2, tk = lane & 3;

    const long long bm = (long long)blockIdx.y * 128;
    const long long bn = (long long)blockIdx.x * 128;

    // ldmatrix per-thread element offsets (floats)
    const int aOff = (wr + (lane & 15)) * LDA + ((lane & 16) ? 4 : 0);
    const int bOff = (wc + (lane & 7) + ((lane & 16) ? 8 : 0)) * LDA
                     + ((lane & 8) ? 4 : 0);

    float c[4][8][4];
    #pragma unroll
    for (int mi = 0; mi < 4; mi++)
        #pragma unroll
        for (int nj = 0; nj < 8; nj++)
            #pragma unroll
            for (int r = 0; r < 4; r++) c[mi][nj][r] = 0.f;

    auto stage = [&](int s, int k0) {
        float* a = sm + s * 2 * TILEF;
        float* b = a + TILEF;
        #pragma unroll
        for (int it = 0; it < 8; it++) {
            int f = it * 128 + tid, row = f >> 3, c4 = f & 7;
            cp_async16(smem_u32(a + row * LDA + c4 * 4),
                       A + (bm + row) * DD + k0 + c4 * 4);
            cp_async16(smem_u32(b + row * LDA + c4 * 4),
                       Bt + (bn + row) * DD + k0 + c4 * 4);
        }
    };

    stage(0, 0);            CP_COMMIT();
    stage(1, GBK);          CP_COMMIT();

    const int NKT = DD / GBK;  // 32
    for (int kt = 0; kt < NKT; kt++) {
        if (kt + 2 < NKT) { CP_WAIT1(); } else { CP_WAIT0(); }
        __syncthreads();

        int buf = kt % 3;
        if (kt + 2 < NKT) { stage((kt + 2) % 3, (kt + 2) * GBK); CP_COMMIT(); }

        const float* a = sm + buf * 2 * TILEF;
        const float* b = a + TILEF;
        uint32_t aBase = smem_u32(a + aOff);
        uint32_t bBase = smem_u32(b + bOff);

        #pragma unroll
        for (int k8 = 0; k8 < 4; k8++) {
            uint32_t av[4][4], bv[4][4];
            #pragma unroll
            for (int mi = 0; mi < 4; mi++)
                LDSM_X4(av[mi], aBase + (mi * 16 * LDA + k8 * 8) * 4);
            #pragma unroll
            for (int p = 0; p < 4; p++)
                LDSM_X4(bv[p], bBase + (p * 16 * LDA + k8 * 8) * 4);
            #pragma unroll
            for (int mi = 0; mi < 4; mi++)
                #pragma unroll
                for (int p = 0; p < 4; p++) {
                    mma_tf32(c[mi][2 * p],     av[mi][0], av[mi][1], av[mi][2], av[mi][3],
                             bv[p][0], bv[p][1]);
                    mma_tf32(c[mi][2 * p + 1], av[mi][0], av[mi][1], av[mi][2], av[mi][3],
                             bv[p][2], bv[p][3]);
                }
        }
        __syncthreads();
    }

    // Epilogue
    #pragma unroll
    for (int mi = 0; mi < 4; mi++) {
        long long row = bm + wr + mi * 16 + tg;
        #pragma unroll
        for (int nj = 0; nj < 8; nj++) {
            long long col = bn + wc + nj * 8 + 2 * tk;
            float2 v0 = make_float2(c[mi][nj][0] * scale, c[mi][nj][1] * scale);
            float2 v1 = make_float2(c[mi][nj][2] * scale, c[mi][nj][3] * scale);
            if (round_out) {
                v0.x = to_tf32(v0.x); v0.y = to_tf32(v0.y);
                v1.x = to_tf32(v1.x); v1.y = to_tf32(v1.y);
            }
            *reinterpret_cast<float2*>(&C[row * DD + col]) = v0;
            *reinterpret_cast<float2*>(&C[(row + 8) * DD + col]) = v1;
        }
    }
}

// ===========================================================================
// Flash attention, tf32 mma. CTA = 128 q-rows of one (b,h), 8 warps
// (warp = 16 q-rows). cp.async double-buffered K/V, ldmatrix Q/K/P frags.
// ===========================================================================
#define ALDK 68
#define ALDV 72

__global__ __launch_bounds__(256, 1) void attn_mma(
    const float* __restrict__ Q, const float* __restrict__ K,
    const float* __restrict__ V, const float* __restrict__ bias,
    float* __restrict__ O)
{
    extern __shared__ float sm[];
    float* Qs = sm;                          // [128][68]
    float* Ks = Qs + 128 * ALDK;             // [2][64][68]
    float* Vs = Ks + 2 * 64 * ALDK;          // [2][64][72]
    float* Ps = Vs + 2 * 64 * ALDV;          // [128][68]

    const int tid = threadIdx.x, lane = tid & 31, wid = tid >> 5;
    const int tg = lane >> 2, tk = lane & 3;
    const int bh = blockIdx.y, b = bh >> 4, h = bh & 15;
    const int q0 = blockIdx.x * 128;

    const float* qbase = Q + ((long long)(b * LL + q0)) * DD + h * DHH;
    const float* kbase = K + ((long long)(b * LL)) * DD + h * DHH;
    const float* vbase = V + ((long long)(b * LL)) * DD + h * DHH;

    // ldmatrix element offsets (floats)
    const int aOffQ = (wid * 16 + (lane & 15)) * ALDK + ((lane & 16) ? 4 : 0);
    const int bOffK = ((lane & 7) + ((lane & 16) ? 8 : 0)) * ALDK
                      + ((lane & 8) ? 4 : 0);
    const int aOffP = aOffQ;   // Ps has same pitch/row mapping as Qs

    auto stageKV = [&](int buf, int kt) {
        float* ks = Ks + buf * 64 * ALDK;
        float* vs = Vs + buf * 64 * ALDV;
        const int k0 = kt * 64;
        #pragma unroll
        for (int it = 0; it < 4; it++) {
            int f = it * 256 + tid, row = f >> 4, c4 = f & 15;
            cp_async16(smem_u32(ks + row * ALDK + c4 * 4),
                       kbase + (long long)(k0 + row) * DD + c4 * 4);
            cp_async16(smem_u32(vs + row * ALDV + c4 * 4),
                       vbase + (long long)(k0 + row) * DD + c4 * 4);
        }
    };

    // Prologue: stage Q + tile 0
    #pragma unroll
    for (int it = 0; it < 8; it++) {
        int f = it * 256 + tid, row = f >> 4, c4 = f & 15;
        cp_async16(smem_u32(Qs + row * ALDK + c4 * 4),
                   qbase + (long long)row * DD + c4 * 4);
    }
    stageKV(0, 0);
    CP_COMMIT();

    float m0 = -INFINITY, m1 = -INFINITY, l0 = 0.f, l1 = 0.f;
    float o[8][4];
    #pragma unroll
    for (int j = 0; j < 8; j++)
        #pragma unroll
        for (int r = 0; r < 4; r++) o[j][r] = 0.f;

    float* Pw = Ps + wid * 16 * ALDK;
    const uint32_t qBase = smem_u32(Qs + aOffQ);
    const uint32_t pBase = smem_u32(Ps + aOffP);

    const int NT = LL / 64;  // 32
    for (int kt = 0; kt < NT; kt++) {
        int buf = kt & 1;
        if (kt + 1 < NT) { stageKV(buf ^ 1, kt + 1); CP_COMMIT(); CP_WAIT1(); }
        else            { CP_WAIT0(); }
        __syncthreads();

        const float* vs = Vs + buf * 64 * ALDV;
        const uint32_t kBase = smem_u32(Ks + buf * 64 * ALDK + bOffK);

        // S = Q @ K^T : warp 16x64
        float s[8][4];
        #pragma unroll
        for (int j = 0; j < 8; j++)
            #pragma unroll
            for (int r = 0; r < 4; r++) s[j][r] = 0.f;

        #pragma unroll
        for (int k8 = 0; k8 < 8; k8++) {
            uint32_t av[4];
            LDSM_X4(av, qBase + (k8 * 8) * 4);
            #pragma unroll
            for (int p = 0; p < 4; p++) {
                uint32_t bv[4];
                LDSM_X4(bv, kBase + (p * 16 * ALDK + k8 * 8) * 4);
                mma_tf32(s[2 * p],     av[0], av[1], av[2], av[3], bv[0], bv[1]);
                mma_tf32(s[2 * p + 1], av[0], av[1], av[2], av[3], bv[2], bv[3]);
            }
        }

        // + bias
        {
            const float* bp = bias + (long long)(q0 + wid * 16 + tg) * LL
                              + kt * 64 + 2 * tk;
            #pragma unroll
            for (int nj = 0; nj < 8; nj++) {
                float2 bv0 = *reinterpret_cast<const float2*>(bp + nj * 8);
                float2 bv1 = *reinterpret_cast<const float2*>(bp + 8 * (long long)LL + nj * 8);
                s[nj][0] += bv0.x; s[nj][1] += bv0.y;
                s[nj][2] += bv1.x; s[nj][3] += bv1.y;
            }
        }

        // Online softmax (rows tg, tg+8; quad reduction over lanes)
        float r0 = -INFINITY, r1 = -INFINITY;
        #pragma unroll
        for (int nj = 0; nj < 8; nj++) {
            r0 = fmaxf(r0, fmaxf(s[nj][0], s[nj][1]));
            r1 = fmaxf(r1, fmaxf(s[nj][2], s[nj][3]));
        }
        r0 = fmaxf(r0, __shfl_xor_sync(0xffffffffu, r0, 1));
        r0 = fmaxf(r0, __shfl_xor_sync(0xffffffffu, r0, 2));
        r1 = fmaxf(r1, __shfl_xor_sync(0xffffffffu, r1, 1));
        r1 = fmaxf(r1, __shfl_xor_sync(0xffffffffu, r1, 2));
        float m0n = fmaxf(m0, r0), m1n = fmaxf(m1, r1);
        float al0 = __expf(m0 - m0n), al1 = __expf(m1 - m1n);
        float s0 = 0.f, s1 = 0.f;
        #pragma unroll
        for (int nj = 0; nj < 8; nj++) {
            s[nj][0] = __expf(s[nj][0] - m0n);
            s[nj][1] = __expf(s[nj][1] - m0n);
            s[nj][2] = __expf(s[nj][2] - m1n);
            s[nj][3] = __expf(s[nj][3] - m1n);
            s0 += s[nj][0] + s[nj][1];
            s1 += s[nj][2] + s[nj][3];
        }
        s0 += __shfl_xor_sync(0xffffffffu, s0, 1);
        s0 += __shfl_xor_sync(0xffffffffu, s0, 2);
        s1 += __shfl_xor_sync(0xffffffffu, s1, 1);
        s1 += __shfl_xor_sync(0xffffffffu, s1, 2);
        l0 = l0 * al0 + s0;  l1 = l1 * al1 + s1;
        m0 = m0n;  m1 = m1n;
        #pragma unroll
        for (int nj = 0; nj < 8; nj++) {
            o[nj][0] *= al0; o[nj][1] *= al0;
            o[nj][2] *= al1; o[nj][3] *= al1;
        }

        // P -> per-warp smem (C-frag -> A-frag), tf32-rounded
        __syncwarp();
        #pragma unroll
        for (int nj = 0; nj < 8; nj++) {
            *reinterpret_cast<float2*>(&Pw[tg * ALDK + nj * 8 + 2 * tk]) =
                make_float2(to_tf32(s[nj][0]), to_tf32(s[nj][1]));
            *reinterpret_cast<float2*>(&Pw[(tg + 8) * ALDK + nj * 8 + 2 * tk]) =
                make_float2(to_tf32(s[nj][2]), to_tf32(s[nj][3]));
        }
        __syncwarp();

        // O += P @ V  (P via ldmatrix; V B-frag scalar, conflict-free)
        #pragma unroll
        for (int k8 = 0; k8 < 8; k8++) {
            uint32_t av[4];
            LDSM_X4(av, pBase + (k8 * 8) * 4);
            #pragma unroll
            for (int nj = 0; nj < 8; nj++) {
                const float* bp = vs + (k8 * 8 + tk) * ALDV + nj * 8 + tg;
                uint32_t b0 = __float_as_uint(bp[0]);
                uint32_t b1 = __float_as_uint(bp[4 * ALDV]);
                mma_tf32(o[nj], av[0], av[1], av[2], av[3], b0, b1);
            }
        }
        __syncthreads();
    }

    // Epilogue: normalize, round to tf32 (feeds final GEMM), store
    float inv0 = 1.f / l0, inv1 = 1.f / l1;
    float* ob = O + ((long long)(b * LL + q0 + wid * 16 + tg)) * DD + h * DHH;
    #pragma unroll
    for (int nj = 0; nj < 8; nj++) {
        float2 v0 = make_float2(to_tf32(o[nj][0] * inv0), to_tf32(o[nj][1] * inv0));
        float2 v1 = make_float2(to_tf32(o[nj][2] * inv1), to_tf32(o[nj][3] * inv1));
        *reinterpret_cast<float2*>(&ob[nj * 8 + 2 * tk]) = v0;
        *reinterpret_cast<float2*>(&ob[8 * DD + nj * 8 + 2 * tk]) = v1;
    }
}

// ---------------------------------------------------------------------------
extern "C" void kernel_launch(void* const* d_in, const int* in_sizes, int n_in,
                              void* d_out, int out_size)
{
    const float* xq   = (const float*)d_in[0];
    const float* xm   = (const float*)d_in[1];
    const float* bias = (const float*)d_in[2];
    const float* Wq   = (const float*)d_in[3];
    const float* Wk   = (const float*)d_in[4];
    const float* Wv   = (const float*)d_in[5];
    const float* Wo   = (const float*)d_in[6];
    float* out = (float*)d_out;

    float *q, *k, *v, *attn, *rxq, *rxm, *twq, *twk, *twv, *two;
    cudaGetSymbolAddress((void**)&q,    g_q);
    cudaGetSymbolAddress((void**)&k,    g_k);
    cudaGetSymbolAddress((void**)&v,    g_v);
    cudaGetSymbolAddress((void**)&attn, g_attn);
    cudaGetSymbolAddress((void**)&rxq,  g_xq);
    cudaGetSymbolAddress((void**)&rxm,  g_xm);
    cudaGetSymbolAddress((void**)&twq,  g_wq);
    cudaGetSymbolAddress((void**)&twk,  g_wk);
    cudaGetSymbolAddress((void**)&twv,  g_wv);
    cudaGetSymbolAddress((void**)&two,  g_wo);

    // 1) Prep: round activations; transpose+round weights to [N,K]
    const int N4X = ROWS * DD / 4;
    round_tf32<<<(N4X + 255) / 256, 256>>>(xq, rxq, N4X);
    round_tf32<<<(N4X + 255) / 256, 256>>>(xm, rxm, N4X);
    dim3 tb(32, 8), tg(DD / 32, DD / 32);
    transpose_tf32<<<tg, tb>>>(Wq, twq);
    transpose_tf32<<<tg, tb>>>(Wk, twk);
    transpose_tf32<<<tg, tb>>>(Wv, twv);
    transpose_tf32<<<tg, tb>>>(Wo, two);

    // 2) Projections
    const int GEMM_SMEM = 3 * 2 * TILEF * 4;  // 110592
    cudaFuncSetAttribute(gemm_mma, cudaFuncAttributeMaxDynamicSharedMemorySize, GEMM_SMEM);
    dim3 gg(DD / 128, ROWS / 128);   // (8, 32) = 256 CTAs
    gemm_mma<<<gg, 128, GEMM_SMEM>>>(rxq, twq, q, 0.125f, 1);
    gemm_mma<<<gg, 128, GEMM_SMEM>>>(rxm, twk, k, 1.0f, 1);
    gemm_mma<<<gg, 128, GEMM_SMEM>>>(rxm, twv, v, 1.0f, 1);

    // 3) Attention
    const int ATTN_SMEM = (128 * ALDK + 2 * 64 * ALDK + 2 * 64 * ALDV + 128 * ALDK) * 4;
    cudaFuncSetAttribute(attn_mma, cudaFuncAttributeMaxDynamicSharedMemorySize, ATTN_SMEM);
    dim3 ga(LL / 128, BB * HH);      // (16, 32)
    attn_mma<<<ga, 256, ATTN_SMEM>>>(q, k, v, bias, attn);

    // 4) Output projection (no rounding — final answer)
    gemm_mma<<<gg, 128, GEMM_SMEM>>>(attn, two, out, 1.0f, 0);
}

// round 5
// speedup vs baseline: 5.6682x; 2.0605x over previous
#include <cuda_runtime.h>
#include <cuda_fp16.h>
#include <math.h>
#include <stdint.h>

#define BB 2
#define LL 2048
#define DD 1024
#define HH 16
#define DHH 64
#define ROWS (BB*LL)   // 4096

// Scratch (allocation-free rule: __device__ globals), all fp16 intermediates
__device__ __half g_q[ROWS*DD];
__device__ __half g_k[ROWS*DD];
__device__ __half g_v[ROWS*DD];
__device__ __half g_attn[ROWS*DD];
__device__ __half g_xq[ROWS*DD];
__device__ __half g_xm[ROWS*DD];
__device__ __half g_wq[DD*DD];   // transposed [n][k]
__device__ __half g_wk[DD*DD];
__device__ __half g_wv[DD*DD];
__device__ __half g_wo[DD*DD];

// ===========================================================================
// Helpers (plain compute_103 PTX: mma.sync fp16, ldmatrix, cp.async)
// ===========================================================================
__device__ __forceinline__ uint32_t smem_u32(const void* p) {
    uint32_t a;
    asm("{ .reg .u64 t; cvta.to.shared.u64 t, %1; cvt.u32.u64 %0, t; }"
        : "=r"(a) : "l"(p));
    return a;
}
__device__ __forceinline__ void mma_f16(float c[4],
    uint32_t a0, uint32_t a1, uint32_t a2, uint32_t a3,
    uint32_t b0, uint32_t b1)
{
    asm volatile(
        "mma.sync.aligned.m16n8k16.row.col.f32.f16.f16.f32 "
        "{%0,%1,%2,%3}, {%4,%5,%6,%7}, {%8,%9}, {%0,%1,%2,%3};"
        : "+f"(c[0]), "+f"(c[1]), "+f"(c[2]), "+f"(c[3])
        : "r"(a0), "r"(a1), "r"(a2), "r"(a3), "r"(b0), "r"(b1));
}
#define LDSM_X4(r, addr) \
    asm volatile("ldmatrix.sync.aligned.m8n8.x4.shared.b16 {%0,%1,%2,%3}, [%4];" \
        : "=r"((r)[0]), "=r"((r)[1]), "=r"((r)[2]), "=r"((r)[3]) : "r"(addr))
#define LDSM_X4_T(r, addr) \
    asm volatile("ldmatrix.sync.aligned.m8n8.x4.trans.shared.b16 {%0,%1,%2,%3}, [%4];" \
        : "=r"((r)[0]), "=r"((r)[1]), "=r"((r)[2]), "=r"((r)[3]) : "r"(addr))
__device__ __forceinline__ void cp_async16(uint32_t s, const void* g) {
    asm volatile("cp.async.cg.shared.global [%0], [%1], 16;" :: "r"(s), "l"(g));
}
#define CP_COMMIT() asm volatile("cp.async.commit_group;" ::: "memory")
#define CP_WAIT0()  asm volatile("cp.async.wait_group 0;" ::: "memory")
#define CP_WAIT1()  asm volatile("cp.async.wait_group 1;" ::: "memory")

// ===========================================================================
// Prep kernels
// ===========================================================================
__global__ __launch_bounds__(256) void convert_h(
    const float* __restrict__ src, __half* __restrict__ dst, int n4)
{
    int i = blockIdx.x * blockDim.x + threadIdx.x;
    if (i < n4) {
        float4 v = reinterpret_cast<const float4*>(src)[i];
        __half2 h0 = __floats2half2_rn(v.x, v.y);
        __half2 h1 = __floats2half2_rn(v.z, v.w);
        reinterpret_cast<__half2*>(dst)[2 * i]     = h0;
        reinterpret_cast<__half2*>(dst)[2 * i + 1] = h1;
    }
}

// Wt[n][k] = half(W[k][n]), 1024x1024
__global__ __launch_bounds__(256) void transpose_h(
    const float* __restrict__ W, __half* __restrict__ Wt)
{
    __shared__ float t[32][33];
    int x = blockIdx.x * 32 + threadIdx.x;
    int y = blockIdx.y * 32 + threadIdx.y;
    #pragma unroll
    for (int i = 0; i < 32; i += 8)
        t[threadIdx.y + i][threadIdx.x] = W[(long long)(y + i) * DD + x];
    __syncthreads();
    x = blockIdx.y * 32 + threadIdx.x;
    y = blockIdx.x * 32 + threadIdx.y;
    #pragma unroll
    for (int i = 0; i < 32; i += 8)
        Wt[(long long)(y + i) * DD + x] = __float2half_rn(t[threadIdx.x][threadIdx.y + i]);
}

// ===========================================================================
// fp16 mma GEMM: C[M,N] = scale * A[M,K] @ Bt[N,K]^T, fp32 accumulate.
// Block 128x128x32, 128 thr (4 warps, 64x64 warp tile), 3-stage cp.async,
// ldmatrix.x4. Pitch 40 halves (80B): ldmatrix phases conflict-free.
// ===========================================================================
#define GBK 32
#define PA 40
#define TILEH (128 * PA)            // halves per (A or B) stage tile

__global__ __launch_bounds__(128, 2) void gemm_h(
    const __half* __restrict__ A, const __half* __restrict__ Bt,
    void* __restrict__ Cv, float scale, int out_half)
{
    extern __shared__ __half sm[];   // 3 stages x (A tile + B tile)

    const int tid = threadIdx.x, lane = tid & 31, wid = tid >> 5;
    const int wr = (wid & 1) * 64, wc = (wid >> 1) * 64;
    const int tg = lane >> 2, tk = lane & 3;

    const long long bm = (long long)blockIdx.y * 128;
    const long long bn = (long long)blockIdx.x * 128;

    // ldmatrix per-thread offsets (halves)
    const int aOff = (wr + (lane & 15)) * PA + ((lane & 16) ? 8 : 0);
    const int bOff = (wc + (lane & 7) + ((lane & 16) ? 8 : 0)) * PA
                     + ((lane & 8) ? 8 : 0);

    float c[4][8][4];
    #pragma unroll
    for (int mi = 0; mi < 4; mi++)
        #pragma unroll
        for (int nj = 0; nj < 8; nj++)
            #pragma unroll
            for (int r = 0; r < 4; r++) c[mi][nj][r] = 0.f;

    auto stage = [&](int s, int k0) {
        __half* a = sm + s * 2 * TILEH;
        __half* b = a + TILEH;
        #pragma unroll
        for (int it = 0; it < 4; it++) {   // 128 rows x 4 chunks(16B), A and B
            int f = it * 128 + tid, row = f >> 2, ch = f & 3;
            cp_async16(smem_u32(a + row * PA + ch * 8),
                       A + (bm + row) * DD + k0 + ch * 8);
            cp_async16(smem_u32(b + row * PA + ch * 8),
                       Bt + (bn + row) * DD + k0 + ch * 8);
        }
    };

    stage(0, 0);       CP_COMMIT();
    stage(1, GBK);     CP_COMMIT();

    const int NKT = DD / GBK;  // 32
    for (int kt = 0; kt < NKT; kt++) {
        if (kt + 2 < NKT) { CP_WAIT1(); } else { CP_WAIT0(); }
        __syncthreads();

        int buf = kt % 3;
        if (kt + 2 < NKT) { stage((kt + 2) % 3, (kt + 2) * GBK); CP_COMMIT(); }

        const __half* a = sm + buf * 2 * TILEH;
        const __half* b = a + TILEH;
        uint32_t aBase = smem_u32(a + aOff);
        uint32_t bBase = smem_u32(b + bOff);

        #pragma unroll
        for (int k16 = 0; k16 < 2; k16++) {
            uint32_t av[4][4], bv[4][4];
            #pragma unroll
            for (int mi = 0; mi < 4; mi++)
                LDSM_X4(av[mi], aBase + (mi * 16 * PA + k16 * 16) * 2);
            #pragma unroll
            for (int p = 0; p < 4; p++)
                LDSM_X4(bv[p], bBase + (p * 16 * PA + k16 * 16) * 2);
            #pragma unroll
            for (int mi = 0; mi < 4; mi++)
                #pragma unroll
                for (int p = 0; p < 4; p++) {
                    mma_f16(c[mi][2 * p],     av[mi][0], av[mi][1], av[mi][2], av[mi][3],
                            bv[p][0], bv[p][1]);
                    mma_f16(c[mi][2 * p + 1], av[mi][0], av[mi][1], av[mi][2], av[mi][3],
                            bv[p][2], bv[p][3]);
                }
        }
        __syncthreads();
    }

    // Epilogue
    #pragma unroll
    for (int mi = 0; mi < 4; mi++) {
        long long row = bm + wr + mi * 16 + tg;
        #pragma unroll
        for (int nj = 0; nj < 8; nj++) {
            long long col = bn + wc + nj * 8 + 2 * tk;
            if (out_half) {
                __half* C = (__half*)Cv;
                *reinterpret_cast<__half2*>(&C[row * DD + col]) =
                    __floats2half2_rn(c[mi][nj][0] * scale, c[mi][nj][1] * scale);
                *reinterpret_cast<__half2*>(&C[(row + 8) * DD + col]) =
                    __floats2half2_rn(c[mi][nj][2] * scale, c[mi][nj][3] * scale);
            } else {
                float* C = (float*)Cv;
                *reinterpret_cast<float2*>(&C[row * DD + col]) =
                    make_float2(c[mi][nj][0] * scale, c[mi][nj][1] * scale);
                *reinterpret_cast<float2*>(&C[(row + 8) * DD + col]) =
                    make_float2(c[mi][nj][2] * scale, c[mi][nj][3] * scale);
            }
        }
    }
}

// ===========================================================================
// Flash attention, fp16 mma. CTA = 128 q-rows of one (b,h), 8 warps
// (warp = 16 q-rows). cp.async double-buffered K/V; ldmatrix for Q/K/P;
// ldmatrix.trans for V. Pitch 72 halves (144B): conflict-free phases.
// ===========================================================================
#define PK 72

__global__ __launch_bounds__(256, 2) void attn_h(
    const __half* __restrict__ Q, const __half* __restrict__ K,
    const __half* __restrict__ V, const float* __restrict__ bias,
    __half* __restrict__ O)
{
    extern __shared__ __half sm[];
    __half* Qs = sm;                          // [128][72]
    __half* Ks = Qs + 128 * PK;               // [2][64][72]
    __half* Vs = Ks + 2 * 64 * PK;            // [2][64][72]
    __half* Ps = Vs + 2 * 64 * PK;            // [128][72]

    const int tid = threadIdx.x, lane = tid & 31, wid = tid >> 5;
    const int tg = lane >> 2, tk = lane & 3;
    const int bh = blockIdx.y, b = bh >> 4, h = bh & 15;
    const int q0 = blockIdx.x * 128;

    const __half* qbase = Q + ((long long)(b * LL + q0)) * DD + h * DHH;
    const __half* kbase = K + ((long long)(b * LL)) * DD + h * DHH;
    const __half* vbase = V + ((long long)(b * LL)) * DD + h * DHH;

    // ldmatrix offsets (halves)
    const int aOffQ = (wid * 16 + (lane & 15)) * PK + ((lane & 16) ? 8 : 0);
    const int bOffK = ((lane & 7) + ((lane & 16) ? 8 : 0)) * PK + ((lane & 8) ? 8 : 0);
    const int bOffV = ((lane & 7) + ((lane & 8) ? 8 : 0)) * PK + ((lane & 16) ? 8 : 0);

    auto stageKV = [&](int buf, int kt) {
        __half* ks = Ks + buf * 64 * PK;
        __half* vs = Vs + buf * 64 * PK;
        const int k0 = kt * 64;
        #pragma unroll
        for (int it = 0; it < 2; it++) {   // 64 rows x 8 chunks(16B) each
            int f = it * 256 + tid, row = f >> 3, ch = f & 7;
            cp_async16(smem_u32(ks + row * PK + ch * 8),
                       kbase + (long long)(k0 + row) * DD + ch * 8);
            cp_async16(smem_u32(vs + row * PK + ch * 8),
                       vbase + (long long)(k0 + row) * DD + ch * 8);
        }
    };

    // Prologue: stage Q + tile 0
    #pragma unroll
    for (int it = 0; it < 4; it++) {       // 128 rows x 8 chunks
        int f = it * 256 + tid, row = f >> 3, ch = f & 7;
        cp_async16(smem_u32(Qs + row * PK + ch * 8),
                   qbase + (long long)row * DD + ch * 8);
    }
    stageKV(0, 0);
    CP_COMMIT();

    float m0 = -INFINITY, m1 = -INFINITY, l0 = 0.f, l1 = 0.f;
    float o[8][4];
    #pragma unroll
    for (int j = 0; j < 8; j++)
        #pragma unroll
        for (int r = 0; r < 4; r++) o[j][r] = 0.f;

    __half* Pw = Ps + wid * 16 * PK;
    const uint32_t qBase = smem_u32(Qs + aOffQ);
    const uint32_t pBase = smem_u32(Ps + aOffQ);

    const int NT = LL / 64;  // 32
    for (int kt = 0; kt < NT; kt++) {
        int buf = kt & 1;
        if (kt + 1 < NT) { stageKV(buf ^ 1, kt + 1); CP_COMMIT(); CP_WAIT1(); }
        else            { CP_WAIT0(); }
        __syncthreads();

        const uint32_t kBase = smem_u32(Ks + buf * 64 * PK + bOffK);
        const uint32_t vBase = smem_u32(Vs + buf * 64 * PK + bOffV);

        // S = Q @ K^T : warp 16x64
        float s[8][4];
        #pragma unroll
        for (int j = 0; j < 8; j++)
            #pragma unroll
            for (int r = 0; r < 4; r++) s[j][r] = 0.f;

        #pragma unroll
        for (int k16 = 0; k16 < 4; k16++) {
            uint32_t av[4];
            LDSM_X4(av, qBase + (k16 * 16) * 2);
            #pragma unroll
            for (int p = 0; p < 4; p++) {
                uint32_t bv[4];
                LDSM_X4(bv, kBase + (p * 16 * PK + k16 * 16) * 2);
                mma_f16(s[2 * p],     av[0], av[1], av[2], av[3], bv[0], bv[1]);
                mma_f16(s[2 * p + 1], av[0], av[1], av[2], av[3], bv[2], bv[3]);
            }
        }

        // + bias (fp32 global)
        {
            const float* bp = bias + (long long)(q0 + wid * 16 + tg) * LL
                              + kt * 64 + 2 * tk;
            #pragma unroll
            for (int nj = 0; nj < 8; nj++) {
                float2 bv0 = *reinterpret_cast<const float2*>(bp + nj * 8);
                float2 bv1 = *reinterpret_cast<const float2*>(bp + 8 * (long long)LL + nj * 8);
                s[nj][0] += bv0.x; s[nj][1] += bv0.y;
                s[nj][2] += bv1.x; s[nj][3] += bv1.y;
            }
        }

        // Online softmax (rows tg, tg+8; quad reduction)
        float r0 = -INFINITY, r1 = -INFINITY;
        #pragma unroll
        for (int nj = 0; nj < 8; nj++) {
            r0 = fmaxf(r0, fmaxf(s[nj][0], s[nj][1]));
            r1 = fmaxf(r1, fmaxf(s[nj][2], s[nj][3]));
        }
        r0 = fmaxf(r0, __shfl_xor_sync(0xffffffffu, r0, 1));
        r0 = fmaxf(r0, __shfl_xor_sync(0xffffffffu, r0, 2));
        r1 = fmaxf(r1, __shfl_xor_sync(0xffffffffu, r1, 1));
        r1 = fmaxf(r1, __shfl_xor_sync(0xffffffffu, r1, 2));
        float m0n = fmaxf(m0, r0), m1n = fmaxf(m1, r1);
        float al0 = __expf(m0 - m0n), al1 = __expf(m1 - m1n);
        float s0 = 0.f, s1 = 0.f;
        #pragma unroll
        for (int nj = 0; nj < 8; nj++) {
            s[nj][0] = __expf(s[nj][0] - m0n);
            s[nj][1] = __expf(s[nj][1] - m0n);
            s[nj][2] = __expf(s[nj][2] - m1n);
            s[nj][3] = __expf(s[nj][3] - m1n);
            s0 += s[nj][0] + s[nj][1];
            s1 += s[nj][2] + s[nj][3];
        }
        s0 += __shfl_xor_sync(0xffffffffu, s0, 1);
        s0 += __shfl_xor_sync(0xffffffffu, s0, 2);
        s1 += __shfl_xor_sync(0xffffffffu, s1, 1);
        s1 += __shfl_xor_sync(0xffffffffu, s1, 2);
        l0 = l0 * al0 + s0;  l1 = l1 * al1 + s1;
        m0 = m0n;  m1 = m1n;
        #pragma unroll
        for (int nj = 0; nj < 8; nj++) {
            o[nj][0] *= al0; o[nj][1] *= al0;
            o[nj][2] *= al1; o[nj][3] *= al1;
        }

        // P -> per-warp smem (C-frag -> A-frag), fp16
        __syncwarp();
        #pragma unroll
        for (int nj = 0; nj < 8; nj++) {
            *reinterpret_cast<__half2*>(&Pw[tg * PK + nj * 8 + 2 * tk]) =
                __floats2half2_rn(s[nj][0], s[nj][1]);
            *reinterpret_cast<__half2*>(&Pw[(tg + 8) * PK + nj * 8 + 2 * tk]) =
                __floats2half2_rn(s[nj][2], s[nj][3]);
        }
        __syncwarp();

        // O += P @ V  (P via ldmatrix, V via ldmatrix.trans)
        #pragma unroll
        for (int k16 = 0; k16 < 4; k16++) {
            uint32_t av[4];
            LDSM_X4(av, pBase + (k16 * 16) * 2);
            #pragma unroll
            for (int p = 0; p < 4; p++) {
                uint32_t bv[4];
                LDSM_X4_T(bv, vBase + (k16 * 16 * PK + p * 16) * 2);
                mma_f16(o[2 * p],     av[0], av[1], av[2], av[3], bv[0], bv[1]);
                mma_f16(o[2 * p + 1], av[0], av[1], av[2], av[3], bv[2], bv[3]);
            }
        }
        __syncthreads();
    }

    // Epilogue: normalize, store fp16 (feeds final GEMM)
    float inv0 = 1.f / l0, inv1 = 1.f / l1;
    __half* ob = O + ((long long)(b * LL + q0 + wid * 16 + tg)) * DD + h * DHH;
    #pragma unroll
    for (int nj = 0; nj < 8; nj++) {
        *reinterpret_cast<__half2*>(&ob[nj * 8 + 2 * tk]) =
            __floats2half2_rn(o[nj][0] * inv0, o[nj][1] * inv0);
        *reinterpret_cast<__half2*>(&ob[8 * DD + nj * 8 + 2 * tk]) =
            __floats2half2_rn(o[nj][2] * inv1, o[nj][3] * inv1);
    }
}

// ---------------------------------------------------------------------------
extern "C" void kernel_launch(void* const* d_in, const int* in_sizes, int n_in,
                              void* d_out, int out_size)
{
    const float* xq   = (const float*)d_in[0];
    const float* xm   = (const float*)d_in[1];
    const float* bias = (const float*)d_in[2];
    const float* Wq   = (const float*)d_in[3];
    const float* Wk   = (const float*)d_in[4];
    const float* Wv   = (const float*)d_in[5];
    const float* Wo   = (const float*)d_in[6];
    float* out = (float*)d_out;

    __half *q, *k, *v, *attn, *hxq, *hxm, *twq, *twk, *twv, *two;
    cudaGetSymbolAddress((void**)&q,    g_q);
    cudaGetSymbolAddress((void**)&k,    g_k);
    cudaGetSymbolAddress((void**)&v,    g_v);
    cudaGetSymbolAddress((void**)&attn, g_attn);
    cudaGetSymbolAddress((void**)&hxq,  g_xq);
    cudaGetSymbolAddress((void**)&hxm,  g_xm);
    cudaGetSymbolAddress((void**)&twq,  g_wq);
    cudaGetSymbolAddress((void**)&twk,  g_wk);
    cudaGetSymbolAddress((void**)&twv,  g_wv);
    cudaGetSymbolAddress((void**)&two,  g_wo);

    // 1) Prep: convert activations; transpose+convert weights to [N,K] fp16
    const int N4X = ROWS * DD / 4;
    convert_h<<<(N4X + 255) / 256, 256>>>(xq, hxq, N4X);
    convert_h<<<(N4X + 255) / 256, 256>>>(xm, hxm, N4X);
    dim3 tb(32, 8), tg(DD / 32, DD / 32);
    transpose_h<<<tg, tb>>>(Wq, twq);
    transpose_h<<<tg, tb>>>(Wk, twk);
    transpose_h<<<tg, tb>>>(Wv, twv);
    transpose_h<<<tg, tb>>>(Wo, two);

    // 2) Projections (fp16 out)
    const int GEMM_SMEM = 3 * 2 * TILEH * 2;  // 61440
    cudaFuncSetAttribute(gemm_h, cudaFuncAttributeMaxDynamicSharedMemorySize, GEMM_SMEM);
    dim3 gg(DD / 128, ROWS / 128);   // (8, 32) = 256 CTAs
    gemm_h<<<gg, 128, GEMM_SMEM>>>(hxq, twq, q, 0.125f, 1);
    gemm_h<<<gg, 128, GEMM_SMEM>>>(hxm, twk, k, 1.0f, 1);
    gemm_h<<<gg, 128, GEMM_SMEM>>>(hxm, twv, v, 1.0f, 1);

    // 3) Attention (fp16 in/out, fp32 softmax)
    const int ATTN_SMEM = (128 * PK + 2 * 64 * PK + 2 * 64 * PK + 128 * PK) * 2; // 73728
    cudaFuncSetAttribute(attn_h, cudaFuncAttributeMaxDynamicSharedMemorySize, ATTN_SMEM);
    dim3 ga(LL / 128, BB * HH);      // (16, 32)
    attn_h<<<ga, 256, ATTN_SMEM>>>(q, k, v, bias, attn);

    // 4) Output projection (fp32 out — final answer)
    gemm_h<<<gg, 128, GEMM_SMEM>>>(attn, two, out, 1.0f, 0);
}

// round 6
// speedup vs baseline: 5.7480x; 1.0141x over previous
#include <cuda_runtime.h>
#include <cuda_fp16.h>
#include <math.h>
#include <stdint.h>

#define BB 2
#define LL 2048
#define DD 1024
#define HH 16
#define DHH 64
#define ROWS (BB*LL)   // 4096

// Scratch (allocation-free rule: __device__ globals), all fp16 intermediates
__device__ __half g_q[ROWS*DD];
__device__ __half g_k[ROWS*DD];
__device__ __half g_v[ROWS*DD];
__device__ __half g_attn[ROWS*DD];
__device__ __half g_xq[ROWS*DD];
__device__ __half g_xm[ROWS*DD];
__device__ __half g_wq[DD*DD];   // transposed [n][k]
__device__ __half g_wk[DD*DD];
__device__ __half g_wv[DD*DD];
__device__ __half g_wo[DD*DD];

// ===========================================================================
// Helpers (plain compute_103 PTX: mma.sync fp16, ldmatrix, cp.async)
// ===========================================================================
__device__ __forceinline__ uint32_t smem_u32(const void* p) {
    uint32_t a;
    asm("{ .reg .u64 t; cvta.to.shared.u64 t, %1; cvt.u32.u64 %0, t; }"
        : "=r"(a) : "l"(p));
    return a;
}
__device__ __forceinline__ void mma_f16(float c[4],
    uint32_t a0, uint32_t a1, uint32_t a2, uint32_t a3,
    uint32_t b0, uint32_t b1)
{
    asm volatile(
        "mma.sync.aligned.m16n8k16.row.col.f32.f16.f16.f32 "
        "{%0,%1,%2,%3}, {%4,%5,%6,%7}, {%8,%9}, {%0,%1,%2,%3};"
        : "+f"(c[0]), "+f"(c[1]), "+f"(c[2]), "+f"(c[3])
        : "r"(a0), "r"(a1), "r"(a2), "r"(a3), "r"(b0), "r"(b1));
}
#define LDSM_X4(r, addr) \
    asm volatile("ldmatrix.sync.aligned.m8n8.x4.shared.b16 {%0,%1,%2,%3}, [%4];" \
        : "=r"((r)[0]), "=r"((r)[1]), "=r"((r)[2]), "=r"((r)[3]) : "r"(addr))
#define LDSM_X4_T(r, addr) \
    asm volatile("ldmatrix.sync.aligned.m8n8.x4.trans.shared.b16 {%0,%1,%2,%3}, [%4];" \
        : "=r"((r)[0]), "=r"((r)[1]), "=r"((r)[2]), "=r"((r)[3]) : "r"(addr))
__device__ __forceinline__ void cp_async16(uint32_t s, const void* g) {
    asm volatile("cp.async.cg.shared.global [%0], [%1], 16;" :: "r"(s), "l"(g));
}
#define CP_COMMIT() asm volatile("cp.async.commit_group;" ::: "memory")
#define CP_WAIT0()  asm volatile("cp.async.wait_group 0;" ::: "memory")
#define CP_WAIT1()  asm volatile("cp.async.wait_group 1;" ::: "memory")

// ===========================================================================
// Prep kernels (fused across inputs via blockIdx.z)
// ===========================================================================
__global__ __launch_bounds__(256) void convert_h2(
    const float* __restrict__ s0, __half* __restrict__ d0,
    const float* __restrict__ s1, __half* __restrict__ d1, int n4)
{
    const float* src = blockIdx.z ? s1 : s0;
    __half* dst      = blockIdx.z ? d1 : d0;
    int i = blockIdx.x * blockDim.x + threadIdx.x;
    if (i < n4) {
        float4 v = reinterpret_cast<const float4*>(src)[i];
        reinterpret_cast<__half2*>(dst)[2 * i]     = __floats2half2_rn(v.x, v.y);
        reinterpret_cast<__half2*>(dst)[2 * i + 1] = __floats2half2_rn(v.z, v.w);
    }
}

// Wt[n][k] = half(W[k][n]), 1024x1024, 4 weights in one launch
__global__ __launch_bounds__(256) void transpose_h4(
    const float* __restrict__ W0, __half* __restrict__ T0,
    const float* __restrict__ W1, __half* __restrict__ T1,
    const float* __restrict__ W2, __half* __restrict__ T2,
    const float* __restrict__ W3, __half* __restrict__ T3)
{
    const float* W; __half* Wt;
    switch (blockIdx.z) {
        case 0:  W = W0; Wt = T0; break;
        case 1:  W = W1; Wt = T1; break;
        case 2:  W = W2; Wt = T2; break;
        default: W = W3; Wt = T3; break;
    }
    __shared__ float t[32][33];
    int x = blockIdx.x * 32 + threadIdx.x;
    int y = blockIdx.y * 32 + threadIdx.y;
    #pragma unroll
    for (int i = 0; i < 32; i += 8)
        t[threadIdx.y + i][threadIdx.x] = W[(long long)(y + i) * DD + x];
    __syncthreads();
    x = blockIdx.y * 32 + threadIdx.x;
    y = blockIdx.x * 32 + threadIdx.y;
    #pragma unroll
    for (int i = 0; i < 32; i += 8)
        Wt[(long long)(y + i) * DD + x] = __float2half_rn(t[threadIdx.x][threadIdx.y + i]);
}

// ===========================================================================
// fp16 mma GEMM: C[M,N] = scale * A[M,K] @ Bt[N,K]^T, fp32 accumulate.
// Block 128x128x32, 128 thr (4 warps, 64x64 warp tile), 3-stage cp.async.
// ===========================================================================
#define GBK 32
#define PA 40
#define TILEH (128 * PA)            // halves per (A or B) stage tile

__global__ __launch_bounds__(128, 2) void gemm_h(
    const __half* __restrict__ A, const __half* __restrict__ Bt,
    void* __restrict__ Cv, float scale, int out_half)
{
    extern __shared__ __half sm[];

    const int tid = threadIdx.x, lane = tid & 31, wid = tid >> 5;
    const int wr = (wid & 1) * 64, wc = (wid >> 1) * 64;
    const int tg = lane >> 2, tk = lane & 3;

    const long long bm = (long long)blockIdx.y * 128;
    const long long bn = (long long)blockIdx.x * 128;

    const int aOff = (wr + (lane & 15)) * PA + ((lane & 16) ? 8 : 0);
    const int bOff = (wc + (lane & 7) + ((lane & 16) ? 8 : 0)) * PA
                     + ((lane & 8) ? 8 : 0);

    float c[4][8][4];
    #pragma unroll
    for (int mi = 0; mi < 4; mi++)
        #pragma unroll
        for (int nj = 0; nj < 8; nj++)
            #pragma unroll
            for (int r = 0; r < 4; r++) c[mi][nj][r] = 0.f;

    auto stage = [&](int s, int k0) {
        __half* a = sm + s * 2 * TILEH;
        __half* b = a + TILEH;
        #pragma unroll
        for (int it = 0; it < 4; it++) {
            int f = it * 128 + tid, row = f >> 2, ch = f & 3;
            cp_async16(smem_u32(a + row * PA + ch * 8),
                       A + (bm + row) * DD + k0 + ch * 8);
            cp_async16(smem_u32(b + row * PA + ch * 8),
                       Bt + (bn + row) * DD + k0 + ch * 8);
        }
    };

    stage(0, 0);       CP_COMMIT();
    stage(1, GBK);     CP_COMMIT();

    const int NKT = DD / GBK;  // 32
    for (int kt = 0; kt < NKT; kt++) {
        if (kt + 2 < NKT) { CP_WAIT1(); } else { CP_WAIT0(); }
        __syncthreads();

        int buf = kt % 3;
        if (kt + 2 < NKT) { stage((kt + 2) % 3, (kt + 2) * GBK); CP_COMMIT(); }

        const __half* a = sm + buf * 2 * TILEH;
        const __half* b = a + TILEH;
        uint32_t aBase = smem_u32(a + aOff);
        uint32_t bBase = smem_u32(b + bOff);

        #pragma unroll
        for (int k16 = 0; k16 < 2; k16++) {
            uint32_t av[4][4], bv[4][4];
            #pragma unroll
            for (int mi = 0; mi < 4; mi++)
                LDSM_X4(av[mi], aBase + (mi * 16 * PA + k16 * 16) * 2);
            #pragma unroll
            for (int p = 0; p < 4; p++)
                LDSM_X4(bv[p], bBase + (p * 16 * PA + k16 * 16) * 2);
            #pragma unroll
            for (int mi = 0; mi < 4; mi++)
                #pragma unroll
                for (int p = 0; p < 4; p++) {
                    mma_f16(c[mi][2 * p],     av[mi][0], av[mi][1], av[mi][2], av[mi][3],
                            bv[p][0], bv[p][1]);
                    mma_f16(c[mi][2 * p + 1], av[mi][0], av[mi][1], av[mi][2], av[mi][3],
                            bv[p][2], bv[p][3]);
                }
        }
        __syncthreads();
    }

    #pragma unroll
    for (int mi = 0; mi < 4; mi++) {
        long long row = bm + wr + mi * 16 + tg;
        #pragma unroll
        for (int nj = 0; nj < 8; nj++) {
            long long col = bn + wc + nj * 8 + 2 * tk;
            if (out_half) {
                __half* C = (__half*)Cv;
                *reinterpret_cast<__half2*>(&C[row * DD + col]) =
                    __floats2half2_rn(c[mi][nj][0] * scale, c[mi][nj][1] * scale);
                *reinterpret_cast<__half2*>(&C[(row + 8) * DD + col]) =
                    __floats2half2_rn(c[mi][nj][2] * scale, c[mi][nj][3] * scale);
            } else {
                float* C = (float*)Cv;
                *reinterpret_cast<float2*>(&C[row * DD + col]) =
                    make_float2(c[mi][nj][0] * scale, c[mi][nj][1] * scale);
                *reinterpret_cast<float2*>(&C[(row + 8) * DD + col]) =
                    make_float2(c[mi][nj][2] * scale, c[mi][nj][3] * scale);
            }
        }
    }
}

// ===========================================================================
// Flash attention, fp16 mma. CTA = 128 q-rows of one (b,h), 8 warps.
// Bias is prefetched into the S accumulator registers one tile ahead
// (s[][] is dead after the P-store), hiding its L2 latency under PV-MMA.
// ===========================================================================
#define PK 72

__global__ __launch_bounds__(256, 2) void attn_h(
    const __half* __restrict__ Q, const __half* __restrict__ K,
    const __half* __restrict__ V, const float* __restrict__ bias,
    __half* __restrict__ O)
{
    extern __shared__ __half sm[];
    __half* Qs = sm;                          // [128][72]
    __half* Ks = Qs + 128 * PK;               // [2][64][72]
    __half* Vs = Ks + 2 * 64 * PK;            // [2][64][72]
    __half* Ps = Vs + 2 * 64 * PK;            // [128][72]

    const int tid = threadIdx.x, lane = tid & 31, wid = tid >> 5;
    const int tg = lane >> 2, tk = lane & 3;
    const int bh = blockIdx.y, b = bh >> 4, h = bh & 15;
    const int q0 = blockIdx.x * 128;

    const __half* qbase = Q + ((long long)(b * LL + q0)) * DD + h * DHH;
    const __half* kbase = K + ((long long)(b * LL)) * DD + h * DHH;
    const __half* vbase = V + ((long long)(b * LL)) * DD + h * DHH;
    const float*  brow  = bias + (long long)(q0 + wid * 16 + tg) * LL + 2 * tk;

    const int aOffQ = (wid * 16 + (lane & 15)) * PK + ((lane & 16) ? 8 : 0);
    const int bOffK = ((lane & 7) + ((lane & 16) ? 8 : 0)) * PK + ((lane & 8) ? 8 : 0);
    const int bOffV = ((lane & 7) + ((lane & 8) ? 8 : 0)) * PK + ((lane & 16) ? 8 : 0);

    auto stageKV = [&](int buf, int kt) {
        __half* ks = Ks + buf * 64 * PK;
        __half* vs = Vs + buf * 64 * PK;
        const int k0 = kt * 64;
        #pragma unroll
        for (int it = 0; it < 2; it++) {
            int f = it * 256 + tid, row = f >> 3, ch = f & 7;
            cp_async16(smem_u32(ks + row * PK + ch * 8),
                       kbase + (long long)(k0 + row) * DD + ch * 8);
            cp_async16(smem_u32(vs + row * PK + ch * 8),
                       vbase + (long long)(k0 + row) * DD + ch * 8);
        }
    };

    // Prologue: stage Q + tile 0
    #pragma unroll
    for (int it = 0; it < 4; it++) {
        int f = it * 256 + tid, row = f >> 3, ch = f & 7;
        cp_async16(smem_u32(Qs + row * PK + ch * 8),
                   qbase + (long long)row * DD + ch * 8);
    }
    stageKV(0, 0);
    CP_COMMIT();

    float m0 = -INFINITY, m1 = -INFINITY, l0 = 0.f, l1 = 0.f;
    float o[8][4];
    #pragma unroll
    for (int j = 0; j < 8; j++)
        #pragma unroll
        for (int r = 0; r < 4; r++) o[j][r] = 0.f;

    float s[8][4];
    auto load_bias = [&](int kt) {   // fills s[][] with bias for tile kt
        const float* bp = brow + kt * 64;
        #pragma unroll
        for (int nj = 0; nj < 8; nj++) {
            float2 b0 = *reinterpret_cast<const float2*>(bp + nj * 8);
            float2 b1 = *reinterpret_cast<const float2*>(bp + 8 * (long long)LL + nj * 8);
            s[nj][0] = b0.x; s[nj][1] = b0.y;
            s[nj][2] = b1.x; s[nj][3] = b1.y;
        }
    };
    load_bias(0);

    __half* Pw = Ps + wid * 16 * PK;
    const uint32_t qBase = smem_u32(Qs + aOffQ);
    const uint32_t pBase = smem_u32(Ps + aOffQ);

    const int NT = LL / 64;  // 32
    for (int kt = 0; kt < NT; kt++) {
        int buf = kt & 1;
        if (kt + 1 < NT) { stageKV(buf ^ 1, kt + 1); CP_COMMIT(); CP_WAIT1(); }
        else            { CP_WAIT0(); }
        __syncthreads();

        const uint32_t kBase = smem_u32(Ks + buf * 64 * PK + bOffK);
        const uint32_t vBase = smem_u32(Vs + buf * 64 * PK + bOffV);

        // S = bias + Q @ K^T  (s pre-loaded with bias)
        #pragma unroll
        for (int k16 = 0; k16 < 4; k16++) {
            uint32_t av[4];
            LDSM_X4(av, qBase + (k16 * 16) * 2);
            #pragma unroll
            for (int p = 0; p < 4; p++) {
                uint32_t bv[4];
                LDSM_X4(bv, kBase + (p * 16 * PK + k16 * 16) * 2);
                mma_f16(s[2 * p],     av[0], av[1], av[2], av[3], bv[0], bv[1]);
                mma_f16(s[2 * p + 1], av[0], av[1], av[2], av[3], bv[2], bv[3]);
            }
        }

        // Online softmax (rows tg, tg+8; quad reduction)
        float r0 = -INFINITY, r1 = -INFINITY;
        #pragma unroll
        for (int nj = 0; nj < 8; nj++) {
            r0 = fmaxf(r0, fmaxf(s[nj][0], s[nj][1]));
            r1 = fmaxf(r1, fmaxf(s[nj][2], s[nj][3]));
        }
        r0 = fmaxf(r0, __shfl_xor_sync(0xffffffffu, r0, 1));
        r0 = fmaxf(r0, __shfl_xor_sync(0xffffffffu, r0, 2));
        r1 = fmaxf(r1, __shfl_xor_sync(0xffffffffu, r1, 1));
        r1 = fmaxf(r1, __shfl_xor_sync(0xffffffffu, r1, 2));
        float m0n = fmaxf(m0, r0), m1n = fmaxf(m1, r1);
        float al0 = __expf(m0 - m0n), al1 = __expf(m1 - m1n);
        float s0 = 0.f, s1 = 0.f;
        #pragma unroll
        for (int nj = 0; nj < 8; nj++) {
            s[nj][0] = __expf(s[nj][0] - m0n);
            s[nj][1] = __expf(s[nj][1] - m0n);
            s[nj][2] = __expf(s[nj][2] - m1n);
            s[nj][3] = __expf(s[nj][3] - m1n);
            s0 += s[nj][0] + s[nj][1];
            s1 += s[nj][2] + s[nj][3];
        }
        s0 += __shfl_xor_sync(0xffffffffu, s0, 1);
        s0 += __shfl_xor_sync(0xffffffffu, s0, 2);
        s1 += __shfl_xor_sync(0xffffffffu, s1, 1);
        s1 += __shfl_xor_sync(0xffffffffu, s1, 2);
        l0 = l0 * al0 + s0;  l1 = l1 * al1 + s1;
        m0 = m0n;  m1 = m1n;
        #pragma unroll
        for (int nj = 0; nj < 8; nj++) {
            o[nj][0] *= al0; o[nj][1] *= al0;
            o[nj][2] *= al1; o[nj][3] *= al1;
        }

        // P -> per-warp smem (C-frag -> A-frag), fp16
        __syncwarp();
        #pragma unroll
        for (int nj = 0; nj < 8; nj++) {
            *reinterpret_cast<__half2*>(&Pw[tg * PK + nj * 8 + 2 * tk]) =
                __floats2half2_rn(s[nj][0], s[nj][1]);
            *reinterpret_cast<__half2*>(&Pw[(tg + 8) * PK + nj * 8 + 2 * tk]) =
                __floats2half2_rn(s[nj][2], s[nj][3]);
        }
        __syncwarp();

        // Prefetch next tile's bias into s (dead until next S-MMA);
        // latency hidden under the PV-MMA below.
        load_bias((kt + 1) & (NT - 1));

        // O += P @ V  (P via ldmatrix, V via ldmatrix.trans)
        #pragma unroll
        for (int k16 = 0; k16 < 4; k16++) {
            uint32_t av[4];
            LDSM_X4(av, pBase + (k16 * 16) * 2);
            #pragma unroll
            for (int p = 0; p < 4; p++) {
                uint32_t bv[4];
                LDSM_X4_T(bv, vBase + (k16 * 16 * PK + p * 16) * 2);
                mma_f16(o[2 * p],     av[0], av[1], av[2], av[3], bv[0], bv[1]);
                mma_f16(o[2 * p + 1], av[0], av[1], av[2], av[3], bv[2], bv[3]);
            }
        }
        __syncthreads();
    }

    // Epilogue: normalize, store fp16 (feeds final GEMM)
    float inv0 = 1.f / l0, inv1 = 1.f / l1;
    __half* ob = O + ((long long)(b * LL + q0 + wid * 16 + tg)) * DD + h * DHH;
    #pragma unroll
    for (int nj = 0; nj < 8; nj++) {
        *reinterpret_cast<__half2*>(&ob[nj * 8 + 2 * tk]) =
            __floats2half2_rn(o[nj][0] * inv0, o[nj][1] * inv0);
        *reinterpret_cast<__half2*>(&ob[8 * DD + nj * 8 + 2 * tk]) =
            __floats2half2_rn(o[nj][2] * inv1, o[nj][3] * inv1);
    }
}

// ---------------------------------------------------------------------------
extern "C" void kernel_launch(void* const* d_in, const int* in_sizes, int n_in,
                              void* d_out, int out_size)
{
    const float* xq   = (const float*)d_in[0];
    const float* xm   = (const float*)d_in[1];
    const float* bias = (const float*)d_in[2];
    const float* Wq   = (const float*)d_in[3];
    const float* Wk   = (const float*)d_in[4];
    const float* Wv   = (const float*)d_in[5];
    const float* Wo   = (const float*)d_in[6];
    float* out = (float*)d_out;

    __half *q, *k, *v, *attn, *hxq, *hxm, *twq, *twk, *twv, *two;
    cudaGetSymbolAddress((void**)&q,    g_q);
    cudaGetSymbolAddress((void**)&k,    g_k);
    cudaGetSymbolAddress((void**)&v,    g_v);
    cudaGetSymbolAddress((void**)&attn, g_attn);
    cudaGetSymbolAddress((void**)&hxq,  g_xq);
    cudaGetSymbolAddress((void**)&hxm,  g_xm);
    cudaGetSymbolAddress((void**)&twq,  g_wq);
    cudaGetSymbolAddress((void**)&twk,  g_wk);
    cudaGetSymbolAddress((void**)&twv,  g_wv);
    cudaGetSymbolAddress((void**)&two,  g_wo);

    // 1) Prep (2 launches): convert both activations; transpose 4 weights
    const int N4X = ROWS * DD / 4;
    dim3 cg((N4X + 255) / 256, 1, 2);
    convert_h2<<<cg, 256>>>(xq, hxq, xm, hxm, N4X);
    dim3 tb(32, 8), tg(DD / 32, DD / 32, 4);
    transpose_h4<<<tg, tb>>>(Wq, twq, Wk, twk, Wv, twv, Wo, two);

    // 2) Projections (fp16 out)
    const int GEMM_SMEM = 3 * 2 * TILEH * 2;  // 61440
    cudaFuncSetAttribute(gemm_h, cudaFuncAttributeMaxDynamicSharedMemorySize, GEMM_SMEM);
    dim3 gg(DD / 128, ROWS / 128);
    gemm_h<<<gg, 128, GEMM_SMEM>>>(hxq, twq, q, 0.125f, 1);
    gemm_h<<<gg, 128, GEMM_SMEM>>>(hxm, twk, k, 1.0f, 1);
    gemm_h<<<gg, 128, GEMM_SMEM>>>(hxm, twv, v, 1.0f, 1);

    // 3) Attention (6th launch — ncu -s 5 captures this)
    const int ATTN_SMEM = (128 * PK + 2 * 64 * PK + 2 * 64 * PK + 128 * PK) * 2;
    cudaFuncSetAttribute(attn_h, cudaFuncAttributeMaxDynamicSharedMemorySize, ATTN_SMEM);
    dim3 ga(LL / 128, BB * HH);
    attn_h<<<ga, 256, ATTN_SMEM>>>(q, k, v, bias, attn);

    // 4) Output projection (fp32 out — final answer)
    gemm_h<<<gg, 128, GEMM_SMEM>>>(attn, two, out, 1.0f, 0);
}